// round 14
// baseline (speedup 1.0000x reference)
#include <cuda_runtime.h>
#include <cuda_fp16.h>
#include <cstdint>

// ---------------- problem constants ----------------
#define GB_BN   1200
#define GB_NQ   300
#define GB_GTOT 32768

// ---------------- device scratch (static, allocation-free) ----------------
__device__ __align__(16) __half g_featTh[21770240];              // fp16 pyramid
__device__ __align__(16) float g_sampled[9830400];
__device__ __align__(16) __half g_paramsh[39321600];             // params (fp16)
__device__ __align__(16) __half g_Hh[39321600];                  // H (fp16)
__device__ __align__(16) float g_partial[9830400];
__device__ __align__(16) __half g_qfh[307200];
__device__ __align__(16) __half g_pgwh[8388608];                 // pg_w^T
__device__ __align__(16) __half g_opwh[8388608];                 // op_w^T

// ---------------- packed f32x2 helpers ----------------
__device__ __forceinline__ unsigned long long pack2(float x, float y){
    unsigned long long r;
    asm("mov.b64 %0, {%1,%2};" : "=l"(r) : "f"(x), "f"(y));
    return r;
}
__device__ __forceinline__ float2 unpack2(unsigned long long v){
    float2 r;
    asm("mov.b64 {%0,%1}, %2;" : "=f"(r.x), "=f"(r.y) : "l"(v));
    return r;
}
__device__ __forceinline__ void fma2(unsigned long long &d,
                                     unsigned long long a,
                                     unsigned long long b){
    asm("fma.rn.f32x2 %0, %1, %2, %0;" : "+l"(d) : "l"(a), "l"(b));
}

// ---------------- block-wide sum + sumsq reduce ----------------
__device__ __forceinline__ float2 block_reduce_sum2(float s, float ss, float* red){
    #pragma unroll
    for (int o = 16; o > 0; o >>= 1){
        s  += __shfl_down_sync(0xffffffffu, s,  o);
        ss += __shfl_down_sync(0xffffffffu, ss, o);
    }
    int w = threadIdx.x >> 5;
    if ((threadIdx.x & 31) == 0){ red[w] = s; red[8 + w] = ss; }
    __syncthreads();
    if (threadIdx.x == 0){
        float a = 0.f, b = 0.f;
        #pragma unroll
        for (int i = 0; i < 8; i++){ a += red[i]; b += red[8 + i]; }
        red[16] = a; red[17] = b;
    }
    __syncthreads();
    float2 r = make_float2(red[16], red[17]);
    __syncthreads();
    return r;
}

// ---------------- feat transpose: (B,D,H,W) fp32 -> (B,G,HW,CG) fp16 ----------
__global__ __launch_bounds__(256) void k_transpose(const float* __restrict__ src,
                                                   __half* __restrict__ dst, int HW)
{
    __shared__ float tile[64][65];
    int bg = blockIdx.x;
    int b = bg >> 2, g = bg & 3;
    int s0 = blockIdx.y * 64;
    int tc = threadIdx.x & 63, tr = threadIdx.x >> 6;
    const float* sp = src + ((long long)b * 256 + g * 64) * HW;
    #pragma unroll
    for (int i = 0; i < 16; i++){
        int c = i * 4 + tr;
        int s = s0 + tc;
        tile[c][tc] = (s < HW) ? sp[(long long)c * HW + s] : 0.f;
    }
    __syncthreads();
    __half* dp = dst + (long long)(b * 4 + g) * HW * 64;
    #pragma unroll
    for (int i = 0; i < 16; i++){
        int sl = i * 4 + tr;
        int s = s0 + sl;
        if (s < HW) dp[(long long)s * 64 + tc] = __float2half_rn(tile[tc][sl]);
    }
}

// ---------------- offsets + level softmax + bilinear gather (fp16 feat) -------
__global__ __launch_bounds__(256) void k_sample(const float* __restrict__ qf,
                                                const float* __restrict__ roi,
                                                const float* __restrict__ off_w,
                                                const float* __restrict__ off_b,
                                                const __half* __restrict__ featT,
                                                float* __restrict__ sampled)
{
    __shared__ float s_qf[256];
    __shared__ float s_pt[128][6];
    int bn = blockIdx.x;
    int b  = bn / GB_NQ;
    int tid = threadIdx.x;
    s_qf[tid] = qf[(long long)bn * 256 + tid];
    __syncthreads();

    if (tid < 128){
        const float* wp = off_w + tid * 3;
        float o0 = off_b[tid * 3 + 0];
        float o1 = off_b[tid * 3 + 1];
        float o2 = off_b[tid * 3 + 2];
        #pragma unroll 8
        for (int k = 0; k < 256; k++){
            float q = s_qf[k];
            o0 = fmaf(q, wp[(long long)k * 384 + 0], o0);
            o1 = fmaf(q, wp[(long long)k * 384 + 1], o1);
            o2 = fmaf(q, wp[(long long)k * 384 + 2], o2);
        }
        float cx = roi[bn * 4 + 0], cy = roi[bn * 4 + 1];
        float z  = roi[bn * 4 + 2], rr = roi[bn * 4 + 3];
        float sc = exp2f(z);
        float rw = sc * exp2f(-0.5f * rr);
        float rh = sc * exp2f( 0.5f * rr);
        float sx = fmaf(o0, rw, cx);
        float sy = fmaf(o1, rh, cy);
        float t  = z + o2 - 3.0f;
        float e0 = expf(-0.5f * t * t);
        float e1 = expf(-0.5f * (t - 1.f) * (t - 1.f));
        float e2 = expf(-0.5f * (t - 2.f) * (t - 2.f));
        float e3 = expf(-0.5f * (t - 3.f) * (t - 3.f));
        float inv = 1.f / (e0 + e1 + e2 + e3);
        s_pt[tid][0] = sx; s_pt[tid][1] = sy;
        s_pt[tid][2] = e0 * inv; s_pt[tid][3] = e1 * inv;
        s_pt[tid][4] = e2 * inv; s_pt[tid][5] = e3 * inv;
    }
    __syncthreads();

    const int   LHh[4]  = {100, 50, 25, 13};
    const int   LWw[4]  = {160, 80, 40, 20};
    const int   LHW[4]  = {16000, 4000, 1000, 260};
    const float LIS[4]  = {0.125f, 0.0625f, 0.03125f, 0.015625f};
    const long long LOFF[4] = {0, 16384000, 20480000, 21504000};

    int c4 = tid & 15;
    #pragma unroll
    for (int it = 0; it < 8; it++){
        int pt = it * 16 + (tid >> 4);
        int g  = pt >> 5;
        float sx = s_pt[pt][0], sy = s_pt[pt][1];
        float4 acc = make_float4(0.f, 0.f, 0.f, 0.f);
        #pragma unroll
        for (int l = 0; l < 4; l++){
            float lw = s_pt[pt][2 + l];
            int W = LWw[l], H = LHh[l];
            const __half* fp = featT + LOFF[l] + (long long)(b * 4 + g) * LHW[l] * 64;
            float px = fmaf(sx, LIS[l], -0.5f);
            float py = fmaf(sy, LIS[l], -0.5f);
            float x0f = floorf(px), y0f = floorf(py);
            int x0 = (int)x0f, y0 = (int)y0f;
            float wx = px - x0f, wy = py - y0f;
            float w00 = (1.f - wx) * (1.f - wy);
            float w10 = wx * (1.f - wy);
            float w01 = (1.f - wx) * wy;
            float w11 = wx * wy;
            auto corner = [&](int xi, int yi, float cw){
                if (xi >= 0 && xi < W && yi >= 0 && yi < H){
                    const __half2* hp = (const __half2*)(fp + ((long long)yi * W + xi) * 64 + c4 * 4);
                    float2 f01 = __half22float2(hp[0]);
                    float2 f23 = __half22float2(hp[1]);
                    float ww = lw * cw;
                    acc.x = fmaf(ww, f01.x, acc.x);
                    acc.y = fmaf(ww, f01.y, acc.y);
                    acc.z = fmaf(ww, f23.x, acc.z);
                    acc.w = fmaf(ww, f23.y, acc.w);
                }
            };
            corner(x0,     y0,     w00);
            corner(x0 + 1, y0,     w10);
            corner(x0,     y0 + 1, w01);
            corner(x0 + 1, y0 + 1, w11);
        }
        *(float4*)(sampled + ((long long)bn * 128 + pt) * 64 + c4 * 4) = acc;
    }
}

// ---------------- fp32 -> fp16 elementwise ----------------
__global__ __launch_bounds__(256) void k_half(const float* __restrict__ in,
                                              __half* __restrict__ hi, int n)
{
    int i = blockIdx.x * 256 + threadIdx.x;
    if (i < n) hi[i] = __float2half_rn(in[i]);
}

// ---------------- transpose + fp16: in[R][C] -> out[C][R] ----------------
__global__ __launch_bounds__(256) void k_tconv(const float* __restrict__ in,
                                               __half* __restrict__ ohi,
                                               int R, int C)
{
    __shared__ float t[32][33];
    int c0 = blockIdx.x * 32, r0 = blockIdx.y * 32;
    int tx = threadIdx.x & 31, ty = threadIdx.x >> 5;
    #pragma unroll
    for (int i = 0; i < 4; i++){
        int r = r0 + ty + i * 8;
        t[ty + i * 8][tx] = in[(size_t)r * C + c0 + tx];
    }
    __syncthreads();
    #pragma unroll
    for (int i = 0; i < 4; i++){
        int c = c0 + ty + i * 8;
        ohi[(size_t)c * R + r0 + tx] = __float2half_rn(t[tx][ty + i * 8]);
    }
}

// ---------------- GEMM via mma.sync fp16, BK=64, templated output -------------
// C = A(MxK) * B(NxK)^T. Tile 128M x 128N, BK=64, 8 warps (2M x 4N, 64x32).
#define SROW 72   // 64 + 8 pad; frag banks (4g+tg) all-distinct, conflict-free

__device__ __forceinline__ uint32_t lds32h(const __half* p){
    return *(const uint32_t*)p;
}

template <typename CT>
__global__ __launch_bounds__(256) void k_mma_gemm(
    const __half* __restrict__ A, int lda,
    const __half* __restrict__ B, int ldb,
    CT* __restrict__ C, int ldc, long long zstride,
    int Mrows, int ksplit, const float* __restrict__ bias)
{
    __shared__ __half sA[128 * SROW];
    __shared__ __half sB[128 * SROW];

    int tid = threadIdx.x;
    int warp = tid >> 5, lane = tid & 31;
    int g = lane >> 2, tg = lane & 3;
    int wm = warp & 1, wn = warp >> 1;      // 2 x 4 warp grid
    int m0 = blockIdx.y * 128;
    int n0 = blockIdx.x * 128;
    int kbase = blockIdx.z * ksplit;
    C += (long long)blockIdx.z * zstride;

    float acc[4][4][4];
    #pragma unroll
    for (int a = 0; a < 4; a++)
        #pragma unroll
        for (int b = 0; b < 4; b++)
            #pragma unroll
            for (int c = 0; c < 4; c++) acc[a][b][c] = 0.f;

    int NK = ksplit >> 6;
    for (int kc = 0; kc < NK; kc++){
        int k0 = kbase + (kc << 6);
        #pragma unroll
        for (int t = 0; t < 4; t++){
            int idx = tid + t * 256;               // 0..1023
            int r = idx >> 3, c8 = (idx & 7) << 3; // 128 rows x 8 uint4
            int m = m0 + r;
            uint4 va = make_uint4(0u,0u,0u,0u);
            if (m < Mrows) va = *(const uint4*)(A + (size_t)m * lda + k0 + c8);
            *(uint4*)&sA[r * SROW + c8] = va;
            size_t gb = (size_t)(n0 + r) * ldb + k0 + c8;
            *(uint4*)&sB[r * SROW + c8] = *(const uint4*)(B + gb);
        }
        __syncthreads();

        #pragma unroll
        for (int ks = 0; ks < 4; ks++){
            int kb = (ks << 4) + (tg << 1);
            uint32_t af[4][4];
            #pragma unroll
            for (int mt = 0; mt < 4; mt++){
                const __half* p = sA + ((wm << 6) + (mt << 4) + g) * SROW + kb;
                af[mt][0] = lds32h(p);
                af[mt][1] = lds32h(p + 8 * SROW);
                af[mt][2] = lds32h(p + 8);
                af[mt][3] = lds32h(p + 8 * SROW + 8);
            }
            #pragma unroll
            for (int nt = 0; nt < 4; nt++){
                const __half* p = sB + ((wn << 5) + (nt << 3) + g) * SROW + kb;
                uint32_t b0 = lds32h(p);
                uint32_t b1 = lds32h(p + 8);
                #pragma unroll
                for (int mt = 0; mt < 4; mt++){
                    asm volatile(
                        "mma.sync.aligned.m16n8k16.row.col.f32.f16.f16.f32 "
                        "{%0,%1,%2,%3}, {%4,%5,%6,%7}, {%8,%9}, {%0,%1,%2,%3};"
                        : "+f"(acc[mt][nt][0]), "+f"(acc[mt][nt][1]),
                          "+f"(acc[mt][nt][2]), "+f"(acc[mt][nt][3])
                        : "r"(af[mt][0]), "r"(af[mt][1]), "r"(af[mt][2]), "r"(af[mt][3]),
                          "r"(b0), "r"(b1));
                }
            }
        }
        __syncthreads();
    }

    #pragma unroll
    for (int mt = 0; mt < 4; mt++){
        #pragma unroll
        for (int half = 0; half < 2; half++){
            int m = m0 + (wm << 6) + (mt << 4) + g + half * 8;
            if (m < Mrows){
                CT* cp = C + (size_t)m * ldc + n0 + (wn << 5) + (tg << 1);
                #pragma unroll
                for (int nt = 0; nt < 4; nt++){
                    float v0 = acc[mt][nt][half * 2 + 0];
                    float v1 = acc[mt][nt][half * 2 + 1];
                    if (bias){
                        int col = n0 + (wn << 5) + (nt << 3) + (tg << 1);
                        v0 += bias[col];
                        v1 += bias[col + 1];
                    }
                    if (sizeof(CT) == 2){
                        *(__half2*)(cp + (nt << 3)) = __floats2half2_rn(v0, v1);
                    } else {
                        *(float2*)((float*)cp + (nt << 3)) = make_float2(v0, v1);
                    }
                }
            }
        }
    }
}

// ---------------- per-(b,n,g) mixing (f32x2, round-12 proven) -----------------
__global__ __launch_bounds__(256) void k_mix(const __half* __restrict__ params,
                                             const float* __restrict__ sampled,
                                             __half* __restrict__ Hh)
{
    __shared__ float s_s[2048];
    __shared__ float s_m[4096];
    __shared__ float red[18];
    int bg = blockIdx.x;
    int bn = bg >> 2, g = bg & 3;
    int tid = threadIdx.x;
    const __half2* P2 = (const __half2*)(params + (long long)bn * GB_GTOT + g * 8192);
    const float* SP = sampled + ((long long)bn * 128 + g * 32) * 64;
    #pragma unroll
    for (int i = 0; i < 8; i++)  s_s[tid + i * 256] = SP[tid + i * 256];
    #pragma unroll
    for (int i = 0; i < 8; i++){
        int idx = tid + i * 256;                 // half2 index into M
        float2 f = __half22float2(P2[idx]);
        s_m[2 * idx]     = f.x;
        s_m[2 * idx + 1] = f.y;
    }
    __syncthreads();

    int j = tid & 31;           // column pair: d = 2j, 2j+1
    int rg = tid >> 5;          // 0..7

    unsigned long long a1[4] = {0ull, 0ull, 0ull, 0ull};
    #pragma unroll
    for (int c4 = 0; c4 < 16; c4++){
        float4 sv0 = *(const float4*)&s_s[(rg     ) * 64 + c4 * 4];
        float4 sv1 = *(const float4*)&s_s[(rg +  8) * 64 + c4 * 4];
        float4 sv2 = *(const float4*)&s_s[(rg + 16) * 64 + c4 * 4];
        float4 sv3 = *(const float4*)&s_s[(rg + 24) * 64 + c4 * 4];
        const float* f0 = (const float*)&sv0;
        const float* f1 = (const float*)&sv1;
        const float* f2 = (const float*)&sv2;
        const float* f3 = (const float*)&sv3;
        #pragma unroll
        for (int cc = 0; cc < 4; cc++){
            float2 m2 = *(const float2*)&s_m[(c4 * 4 + cc) * 64 + 2 * j];
            unsigned long long mp = pack2(m2.x, m2.y);
            fma2(a1[0], pack2(f0[cc], f0[cc]), mp);
            fma2(a1[1], pack2(f1[cc], f1[cc]), mp);
            fma2(a1[2], pack2(f2[cc], f2[cc]), mp);
            fma2(a1[3], pack2(f3[cc], f3[cc]), mp);
        }
    }
    float lsum = 0.f, lss = 0.f;
    float2 u1[4];
    #pragma unroll
    for (int t = 0; t < 4; t++){
        u1[t] = unpack2(a1[t]);
        lsum += u1[t].x + u1[t].y;
        lss  += u1[t].x * u1[t].x + u1[t].y * u1[t].y;
    }
    float2 sv = block_reduce_sum2(lsum, lss, red);
    float mu  = sv.x * (1.f / 2048.f);
    float var = sv.y * (1.f / 2048.f) - mu * mu;
    float inv = rsqrtf(var + 1e-5f);
    #pragma unroll
    for (int t = 0; t < 4; t++){
        float v0 = (u1[t].x - mu) * inv; v0 = v0 > 0.f ? v0 : 0.f;
        float v1 = (u1[t].y - mu) * inv; v1 = v1 > 0.f ? v1 : 0.f;
        *(float2*)&s_s[(rg + 8 * t) * 64 + 2 * j] = make_float2(v0, v1);
    }
    #pragma unroll
    for (int i = 0; i < 8; i++){
        int idx = tid + i * 256;                 // half2 index into S
        float2 f = __half22float2(P2[2048 + idx]);
        s_m[2 * idx]     = f.x;
        s_m[2 * idx + 1] = f.y;
    }
    __syncthreads();

    unsigned long long a2[16];
    #pragma unroll
    for (int i = 0; i < 16; i++) a2[i] = 0ull;
    #pragma unroll
    for (int p4 = 0; p4 < 8; p4++){
        float2 r0 = *(const float2*)&s_s[(p4 * 4 + 0) * 64 + 2 * j];
        float2 r1 = *(const float2*)&s_s[(p4 * 4 + 1) * 64 + 2 * j];
        float2 r2 = *(const float2*)&s_s[(p4 * 4 + 2) * 64 + 2 * j];
        float2 r3 = *(const float2*)&s_s[(p4 * 4 + 3) * 64 + 2 * j];
        unsigned long long rp0 = pack2(r0.x, r0.y);
        unsigned long long rp1 = pack2(r1.x, r1.y);
        unsigned long long rp2 = pack2(r2.x, r2.y);
        unsigned long long rp3 = pack2(r3.x, r3.y);
        #pragma unroll
        for (int i = 0; i < 16; i++){
            float4 s4 = *(const float4*)&s_m[(rg + 8 * i) * 32 + p4 * 4];
            fma2(a2[i], pack2(s4.x, s4.x), rp0);
            fma2(a2[i], pack2(s4.y, s4.y), rp1);
            fma2(a2[i], pack2(s4.z, s4.z), rp2);
            fma2(a2[i], pack2(s4.w, s4.w), rp3);
        }
    }
    lsum = 0.f; lss = 0.f;
    float2 u2[16];
    #pragma unroll
    for (int i = 0; i < 16; i++){
        u2[i] = unpack2(a2[i]);
        lsum += u2[i].x + u2[i].y;
        lss  += u2[i].x * u2[i].x + u2[i].y * u2[i].y;
    }
    sv = block_reduce_sum2(lsum, lss, red);
    mu  = sv.x * (1.f / 8192.f);
    var = sv.y * (1.f / 8192.f) - mu * mu;
    inv = rsqrtf(var + 1e-5f);
    long long base = (long long)bn * GB_GTOT + g * 8192;
    #pragma unroll
    for (int i = 0; i < 16; i++){
        int o = rg + 8 * i;
        float v0 = (u2[i].x - mu) * inv; v0 = v0 > 0.f ? v0 : 0.f;
        float v1 = (u2[i].y - mu) * inv; v1 = v1 > 0.f ? v1 : 0.f;
        *(__half2*)&Hh[base + o * 64 + 2 * j] = __floats2half2_rn(v0, v1);
    }
}

// ---------------- split-K reduce + residual + LN1 affine ----------------
__global__ __launch_bounds__(256) void k_final(const float* __restrict__ qf,
                                               const float* __restrict__ op_b,
                                               const float* __restrict__ ln_g,
                                               const float* __restrict__ ln_b,
                                               const float* __restrict__ partial,
                                               float* __restrict__ out)
{
    __shared__ float red[18];
    int bn = blockIdx.x, j = threadIdx.x;
    float x = qf[(long long)bn * 256 + j] + op_b[j];
    #pragma unroll
    for (int sk = 0; sk < 32; sk++)
        x += partial[((long long)sk * GB_BN + bn) * 256 + j];
    float2 sv = block_reduce_sum2(x, x * x, red);
    float mu  = sv.x * (1.f / 256.f);
    float var = sv.y * (1.f / 256.f) - mu * mu;
    float inv = rsqrtf(var + 1e-5f);
    out[(long long)bn * 256 + j] = fmaf((x - mu) * inv, ln_g[j], ln_b[j]);
}

// ---------------- launcher ----------------
extern "C" void kernel_launch(void* const* d_in, const int* in_sizes, int n_in,
                              void* d_out, int out_size)
{
    (void)in_sizes; (void)n_in; (void)out_size;
    const float* feat[4];
    for (int i = 0; i < 4; i++) feat[i] = (const float*)d_in[i];
    const float* qf    = (const float*)d_in[4];
    const float* roi   = (const float*)d_in[5];
    const float* off_w = (const float*)d_in[6];
    const float* off_b = (const float*)d_in[7];
    const float* pg_w  = (const float*)d_in[8];
    const float* pg_b  = (const float*)d_in[9];
    const float* op_w  = (const float*)d_in[10];
    const float* op_b  = (const float*)d_in[11];
    const float* ln_g  = (const float*)d_in[12];
    const float* ln_b  = (const float*)d_in[13];

    float *sampled, *partial;
    __half *featTh, *paramsh, *Hh, *qfh, *pgwh, *opwh;
    cudaGetSymbolAddress((void**)&featTh,  g_featTh);
    cudaGetSymbolAddress((void**)&sampled, g_sampled);
    cudaGetSymbolAddress((void**)&paramsh, g_paramsh);
    cudaGetSymbolAddress((void**)&partial, g_partial);
    cudaGetSymbolAddress((void**)&Hh,      g_Hh);
    cudaGetSymbolAddress((void**)&qfh,     g_qfh);
    cudaGetSymbolAddress((void**)&pgwh,    g_pgwh);
    cudaGetSymbolAddress((void**)&opwh,    g_opwh);

    const int LHW[4] = {16000, 4000, 1000, 260};
    const long long LOFF[4] = {0, 16384000, 20480000, 21504000};
    for (int l = 0; l < 4; l++)
        k_transpose<<<dim3(16, (LHW[l] + 63) / 64), 256>>>(feat[l], featTh + LOFF[l], LHW[l]);

    // conversions
    k_half<<<(307200 + 255) / 256, 256>>>(qf, qfh, 307200);
    k_tconv<<<dim3(1024, 8),  256>>>(pg_w, pgwh, 256, 32768);   // -> [32768][256]
    k_tconv<<<dim3(8, 1024),  256>>>(op_w, opwh, 32768, 256);   // -> [256][32768]

    k_sample<<<GB_BN, 256>>>(qf, roi, off_w, off_b, featTh, sampled);

    // GEMM1: params(1200x32768, fp16) = qf(1200x256) @ pg_w
    k_mma_gemm<__half><<<dim3(256, 10, 1), 256>>>(
        qfh, 256, pgwh, 256,
        paramsh, 32768, 0LL, GB_BN, 256, pg_b);

    k_mix<<<GB_BN * 4, 256>>>(paramsh, sampled, Hh);

    // GEMM2: partial[z](1200x256, fp32) = H(1200x32768)[k-chunk z] @ op_w
    k_mma_gemm<float><<<dim3(2, 10, 32), 256>>>(
        Hh, 32768, opwh, 32768,
        partial, 256, 307200LL, GB_BN, 1024, (const float*)nullptr);

    k_final<<<GB_BN, 256>>>(qf, op_b, ln_g, ln_b, partial, (float*)d_out);
}

// round 15
// speedup vs baseline: 1.1335x; 1.1335x over previous
#include <cuda_runtime.h>
#include <cuda_fp16.h>
#include <cstdint>

// ---------------- problem constants ----------------
#define GB_BN   1200
#define GB_NQ   300
#define GB_GTOT 32768

// ---------------- device scratch (static, allocation-free) ----------------
__device__ __align__(16) __half g_featTh[21770240];              // fp16 pyramid
__device__ __align__(16) float g_sampled[9830400];
__device__ __align__(16) __half g_paramsh[39321600];             // params (fp16)
__device__ __align__(16) __half g_Hh[39321600];                  // H (fp16)
__device__ __align__(16) float g_partial[9830400];
__device__ __align__(16) __half g_qfh[307200];
__device__ __align__(16) __half g_pgwh[8388608];                 // pg_w^T
__device__ __align__(16) __half g_opwh[8388608];                 // op_w^T

// ---------------- packed f32x2 helpers ----------------
__device__ __forceinline__ unsigned long long pack2(float x, float y){
    unsigned long long r;
    asm("mov.b64 %0, {%1,%2};" : "=l"(r) : "f"(x), "f"(y));
    return r;
}
__device__ __forceinline__ float2 unpack2(unsigned long long v){
    float2 r;
    asm("mov.b64 {%0,%1}, %2;" : "=f"(r.x), "=f"(r.y) : "l"(v));
    return r;
}
__device__ __forceinline__ void fma2(unsigned long long &d,
                                     unsigned long long a,
                                     unsigned long long b){
    asm("fma.rn.f32x2 %0, %1, %2, %0;" : "+l"(d) : "l"(a), "l"(b));
}

// ---------------- block-wide sum + sumsq reduce ----------------
__device__ __forceinline__ float2 block_reduce_sum2(float s, float ss, float* red){
    #pragma unroll
    for (int o = 16; o > 0; o >>= 1){
        s  += __shfl_down_sync(0xffffffffu, s,  o);
        ss += __shfl_down_sync(0xffffffffu, ss, o);
    }
    int w = threadIdx.x >> 5;
    if ((threadIdx.x & 31) == 0){ red[w] = s; red[8 + w] = ss; }
    __syncthreads();
    if (threadIdx.x == 0){
        float a = 0.f, b = 0.f;
        #pragma unroll
        for (int i = 0; i < 8; i++){ a += red[i]; b += red[8 + i]; }
        red[16] = a; red[17] = b;
    }
    __syncthreads();
    float2 r = make_float2(red[16], red[17]);
    __syncthreads();
    return r;
}

// ---------------- feat transpose: (B,D,H,W) fp32 -> (B,G,HW,CG) fp16 ----------
__global__ __launch_bounds__(256) void k_transpose(const float* __restrict__ src,
                                                   __half* __restrict__ dst, int HW)
{
    __shared__ float tile[64][65];
    int bg = blockIdx.x;
    int b = bg >> 2, g = bg & 3;
    int s0 = blockIdx.y * 64;
    int tc = threadIdx.x & 63, tr = threadIdx.x >> 6;
    const float* sp = src + ((long long)b * 256 + g * 64) * HW;
    #pragma unroll
    for (int i = 0; i < 16; i++){
        int c = i * 4 + tr;
        int s = s0 + tc;
        tile[c][tc] = (s < HW) ? sp[(long long)c * HW + s] : 0.f;
    }
    __syncthreads();
    __half* dp = dst + (long long)(b * 4 + g) * HW * 64;
    #pragma unroll
    for (int i = 0; i < 16; i++){
        int sl = i * 4 + tr;
        int s = s0 + sl;
        if (s < HW) dp[(long long)s * 64 + tc] = __float2half_rn(tile[tc][sl]);
    }
}

// ---------------- offsets + level softmax + bilinear gather (fp16 feat) -------
__global__ __launch_bounds__(256) void k_sample(const float* __restrict__ qf,
                                                const float* __restrict__ roi,
                                                const float* __restrict__ off_w,
                                                const float* __restrict__ off_b,
                                                const __half* __restrict__ featT,
                                                float* __restrict__ sampled)
{
    __shared__ float s_qf[256];
    __shared__ float s_pt[128][6];
    int bn = blockIdx.x;
    int b  = bn / GB_NQ;
    int tid = threadIdx.x;
    s_qf[tid] = qf[(long long)bn * 256 + tid];
    __syncthreads();

    if (tid < 128){
        const float* wp = off_w + tid * 3;
        float o0 = off_b[tid * 3 + 0];
        float o1 = off_b[tid * 3 + 1];
        float o2 = off_b[tid * 3 + 2];
        #pragma unroll 8
        for (int k = 0; k < 256; k++){
            float q = s_qf[k];
            o0 = fmaf(q, wp[(long long)k * 384 + 0], o0);
            o1 = fmaf(q, wp[(long long)k * 384 + 1], o1);
            o2 = fmaf(q, wp[(long long)k * 384 + 2], o2);
        }
        float cx = roi[bn * 4 + 0], cy = roi[bn * 4 + 1];
        float z  = roi[bn * 4 + 2], rr = roi[bn * 4 + 3];
        float sc = exp2f(z);
        float rw = sc * exp2f(-0.5f * rr);
        float rh = sc * exp2f( 0.5f * rr);
        float sx = fmaf(o0, rw, cx);
        float sy = fmaf(o1, rh, cy);
        float t  = z + o2 - 3.0f;
        float e0 = expf(-0.5f * t * t);
        float e1 = expf(-0.5f * (t - 1.f) * (t - 1.f));
        float e2 = expf(-0.5f * (t - 2.f) * (t - 2.f));
        float e3 = expf(-0.5f * (t - 3.f) * (t - 3.f));
        float inv = 1.f / (e0 + e1 + e2 + e3);
        s_pt[tid][0] = sx; s_pt[tid][1] = sy;
        s_pt[tid][2] = e0 * inv; s_pt[tid][3] = e1 * inv;
        s_pt[tid][4] = e2 * inv; s_pt[tid][5] = e3 * inv;
    }
    __syncthreads();

    const int   LHh[4]  = {100, 50, 25, 13};
    const int   LWw[4]  = {160, 80, 40, 20};
    const int   LHW[4]  = {16000, 4000, 1000, 260};
    const float LIS[4]  = {0.125f, 0.0625f, 0.03125f, 0.015625f};
    const long long LOFF[4] = {0, 16384000, 20480000, 21504000};

    int c4 = tid & 15;
    #pragma unroll
    for (int it = 0; it < 8; it++){
        int pt = it * 16 + (tid >> 4);
        int g  = pt >> 5;
        float sx = s_pt[pt][0], sy = s_pt[pt][1];
        float4 acc = make_float4(0.f, 0.f, 0.f, 0.f);
        #pragma unroll
        for (int l = 0; l < 4; l++){
            float lw = s_pt[pt][2 + l];
            int W = LWw[l], H = LHh[l];
            const __half* fp = featT + LOFF[l] + (long long)(b * 4 + g) * LHW[l] * 64;
            float px = fmaf(sx, LIS[l], -0.5f);
            float py = fmaf(sy, LIS[l], -0.5f);
            float x0f = floorf(px), y0f = floorf(py);
            int x0 = (int)x0f, y0 = (int)y0f;
            float wx = px - x0f, wy = py - y0f;
            float w00 = (1.f - wx) * (1.f - wy);
            float w10 = wx * (1.f - wy);
            float w01 = (1.f - wx) * wy;
            float w11 = wx * wy;
            auto corner = [&](int xi, int yi, float cw){
                if (xi >= 0 && xi < W && yi >= 0 && yi < H){
                    const __half2* hp = (const __half2*)(fp + ((long long)yi * W + xi) * 64 + c4 * 4);
                    float2 f01 = __half22float2(hp[0]);
                    float2 f23 = __half22float2(hp[1]);
                    float ww = lw * cw;
                    acc.x = fmaf(ww, f01.x, acc.x);
                    acc.y = fmaf(ww, f01.y, acc.y);
                    acc.z = fmaf(ww, f23.x, acc.z);
                    acc.w = fmaf(ww, f23.y, acc.w);
                }
            };
            corner(x0,     y0,     w00);
            corner(x0 + 1, y0,     w10);
            corner(x0,     y0 + 1, w01);
            corner(x0 + 1, y0 + 1, w11);
        }
        *(float4*)(sampled + ((long long)bn * 128 + pt) * 64 + c4 * 4) = acc;
    }
}

// ---------------- fp32 -> fp16 elementwise ----------------
__global__ __launch_bounds__(256) void k_half(const float* __restrict__ in,
                                              __half* __restrict__ hi, int n)
{
    int i = blockIdx.x * 256 + threadIdx.x;
    if (i < n) hi[i] = __float2half_rn(in[i]);
}

// ---------------- transpose + fp16: in[R][C] -> out[C][R] ----------------
__global__ __launch_bounds__(256) void k_tconv(const float* __restrict__ in,
                                               __half* __restrict__ ohi,
                                               int R, int C)
{
    __shared__ float t[32][33];
    int c0 = blockIdx.x * 32, r0 = blockIdx.y * 32;
    int tx = threadIdx.x & 31, ty = threadIdx.x >> 5;
    #pragma unroll
    for (int i = 0; i < 4; i++){
        int r = r0 + ty + i * 8;
        t[ty + i * 8][tx] = in[(size_t)r * C + c0 + tx];
    }
    __syncthreads();
    #pragma unroll
    for (int i = 0; i < 4; i++){
        int c = c0 + ty + i * 8;
        ohi[(size_t)c * R + r0 + tx] = __float2half_rn(t[tx][ty + i * 8]);
    }
}

// ---------------- GEMM via mma.sync fp16, BK=32 (round-12 proven) -------------
// C = A(MxK) * B(NxK)^T. Tile 128M x 128N, BK=32, 8 warps (2M x 4N, 64x32).
#define SROW 40   // 32 + 8 pad; conflict-free (proven)

__device__ __forceinline__ uint32_t lds32h(const __half* p){
    return *(const uint32_t*)p;
}

template <typename CT>
__global__ __launch_bounds__(256) void k_mma_gemm(
    const __half* __restrict__ A, int lda,
    const __half* __restrict__ B, int ldb,
    CT* __restrict__ C, int ldc, long long zstride,
    int Mrows, int ksplit, const float* __restrict__ bias)
{
    __shared__ __half sA[128 * SROW];
    __shared__ __half sB[128 * SROW];

    int tid = threadIdx.x;
    int warp = tid >> 5, lane = tid & 31;
    int g = lane >> 2, tg = lane & 3;
    int wm = warp & 1, wn = warp >> 1;      // 2 x 4 warp grid
    int m0 = blockIdx.y * 128;
    int n0 = blockIdx.x * 128;
    int kbase = blockIdx.z * ksplit;
    C += (long long)blockIdx.z * zstride;

    float acc[4][4][4];
    #pragma unroll
    for (int a = 0; a < 4; a++)
        #pragma unroll
        for (int b = 0; b < 4; b++)
            #pragma unroll
            for (int c = 0; c < 4; c++) acc[a][b][c] = 0.f;

    int NK = ksplit >> 5;
    for (int kc = 0; kc < NK; kc++){
        int k0 = kbase + (kc << 5);
        #pragma unroll
        for (int t = 0; t < 2; t++){
            int idx = tid + t * 256;               // 0..511
            int r = idx >> 2, c8 = (idx & 3) << 3; // 128 rows x 4 uint4
            int m = m0 + r;
            uint4 va = make_uint4(0u,0u,0u,0u);
            if (m < Mrows) va = *(const uint4*)(A + (size_t)m * lda + k0 + c8);
            *(uint4*)&sA[r * SROW + c8] = va;
            size_t gb = (size_t)(n0 + r) * ldb + k0 + c8;
            *(uint4*)&sB[r * SROW + c8] = *(const uint4*)(B + gb);
        }
        __syncthreads();

        #pragma unroll
        for (int ks = 0; ks < 2; ks++){
            int kb = (ks << 4) + (tg << 1);
            uint32_t af[4][4];
            #pragma unroll
            for (int mt = 0; mt < 4; mt++){
                const __half* p = sA + ((wm << 6) + (mt << 4) + g) * SROW + kb;
                af[mt][0] = lds32h(p);
                af[mt][1] = lds32h(p + 8 * SROW);
                af[mt][2] = lds32h(p + 8);
                af[mt][3] = lds32h(p + 8 * SROW + 8);
            }
            #pragma unroll
            for (int nt = 0; nt < 4; nt++){
                const __half* p = sB + ((wn << 5) + (nt << 3) + g) * SROW + kb;
                uint32_t b0 = lds32h(p);
                uint32_t b1 = lds32h(p + 8);
                #pragma unroll
                for (int mt = 0; mt < 4; mt++){
                    asm volatile(
                        "mma.sync.aligned.m16n8k16.row.col.f32.f16.f16.f32 "
                        "{%0,%1,%2,%3}, {%4,%5,%6,%7}, {%8,%9}, {%0,%1,%2,%3};"
                        : "+f"(acc[mt][nt][0]), "+f"(acc[mt][nt][1]),
                          "+f"(acc[mt][nt][2]), "+f"(acc[mt][nt][3])
                        : "r"(af[mt][0]), "r"(af[mt][1]), "r"(af[mt][2]), "r"(af[mt][3]),
                          "r"(b0), "r"(b1));
                }
            }
        }
        __syncthreads();
    }

    #pragma unroll
    for (int mt = 0; mt < 4; mt++){
        #pragma unroll
        for (int half = 0; half < 2; half++){
            int m = m0 + (wm << 6) + (mt << 4) + g + half * 8;
            if (m < Mrows){
                CT* cp = C + (size_t)m * ldc + n0 + (wn << 5) + (tg << 1);
                #pragma unroll
                for (int nt = 0; nt < 4; nt++){
                    float v0 = acc[mt][nt][half * 2 + 0];
                    float v1 = acc[mt][nt][half * 2 + 1];
                    if (bias){
                        int col = n0 + (wn << 5) + (nt << 3) + (tg << 1);
                        v0 += bias[col];
                        v1 += bias[col + 1];
                    }
                    if (sizeof(CT) == 2){
                        *(__half2*)(cp + (nt << 3)) = __floats2half2_rn(v0, v1);
                    } else {
                        *(float2*)((float*)cp + (nt << 3)) = make_float2(v0, v1);
                    }
                }
            }
        }
    }
}

// ---------------- per-(b,n,g) mixing: phase1 f32x2, phase2 HMMA (r13) ---------
#define MROW 40   // pad for S / h1T fp16 tiles (conflict-free)

__global__ __launch_bounds__(256) void k_mix(const __half* __restrict__ params,
                                             const float* __restrict__ sampled,
                                             __half* __restrict__ Hh)
{
    __shared__ float  s_s[2048];          // sampled 32x64 fp32
    __shared__ float  s_m[4096];          // M fp32
    __shared__ __half sS[128 * MROW];     // S fp16, padded
    __shared__ __half h1T[64 * MROW];     // h1^T fp16, padded
    __shared__ float  red[18];
    int bg = blockIdx.x;
    int bn = bg >> 2, g = bg & 3;
    int tid = threadIdx.x;
    const __half2* P2 = (const __half2*)(params + (long long)bn * GB_GTOT + g * 8192);
    const float* SP = sampled + ((long long)bn * 128 + g * 32) * 64;
    #pragma unroll
    for (int i = 0; i < 8; i++)  s_s[tid + i * 256] = SP[tid + i * 256];
    #pragma unroll
    for (int i = 0; i < 8; i++){
        int idx = tid + i * 256;                 // half2 index into M
        float2 f = __half22float2(P2[idx]);
        s_m[2 * idx]     = f.x;
        s_m[2 * idx + 1] = f.y;
        // S fp16 staged into padded tile: S[o][p], o=idx>>4, p=(idx&15)*2
        int o = idx >> 4, pp = (idx & 15) << 1;
        *(__half2*)&sS[o * MROW + pp] = P2[2048 + idx];
    }
    __syncthreads();

    int j = tid & 31;           // column pair: d = 2j, 2j+1
    int rg = tid >> 5;          // 0..7

    // ---- phase 1: h1 = sampled @ M (f32x2) ----
    unsigned long long a1[4] = {0ull, 0ull, 0ull, 0ull};
    #pragma unroll
    for (int c4 = 0; c4 < 16; c4++){
        float4 sv0 = *(const float4*)&s_s[(rg     ) * 64 + c4 * 4];
        float4 sv1 = *(const float4*)&s_s[(rg +  8) * 64 + c4 * 4];
        float4 sv2 = *(const float4*)&s_s[(rg + 16) * 64 + c4 * 4];
        float4 sv3 = *(const float4*)&s_s[(rg + 24) * 64 + c4 * 4];
        const float* f0 = (const float*)&sv0;
        const float* f1 = (const float*)&sv1;
        const float* f2 = (const float*)&sv2;
        const float* f3 = (const float*)&sv3;
        #pragma unroll
        for (int cc = 0; cc < 4; cc++){
            float2 m2 = *(const float2*)&s_m[(c4 * 4 + cc) * 64 + 2 * j];
            unsigned long long mp = pack2(m2.x, m2.y);
            fma2(a1[0], pack2(f0[cc], f0[cc]), mp);
            fma2(a1[1], pack2(f1[cc], f1[cc]), mp);
            fma2(a1[2], pack2(f2[cc], f2[cc]), mp);
            fma2(a1[3], pack2(f3[cc], f3[cc]), mp);
        }
    }
    float lsum = 0.f, lss = 0.f;
    float2 u1[4];
    #pragma unroll
    for (int t = 0; t < 4; t++){
        u1[t] = unpack2(a1[t]);
        lsum += u1[t].x + u1[t].y;
        lss  += u1[t].x * u1[t].x + u1[t].y * u1[t].y;
    }
    float2 sv = block_reduce_sum2(lsum, lss, red);
    float mu  = sv.x * (1.f / 2048.f);
    float var = sv.y * (1.f / 2048.f) - mu * mu;
    float inv = rsqrtf(var + 1e-5f);
    // LN + ReLU + write h1 transposed as fp16: h1T[d][p]
    #pragma unroll
    for (int t = 0; t < 4; t++){
        int p = rg + 8 * t;
        float v0 = (u1[t].x - mu) * inv; v0 = v0 > 0.f ? v0 : 0.f;
        float v1 = (u1[t].y - mu) * inv; v1 = v1 > 0.f ? v1 : 0.f;
        h1T[(2 * j    ) * MROW + p] = __float2half_rn(v0);
        h1T[(2 * j + 1) * MROW + p] = __float2half_rn(v1);
    }
    __syncthreads();

    // ---- phase 2: h2 = S @ h1 via HMMA. warp = m-tile (16 o-rows) ----
    int warp = tid >> 5, lane = tid & 31;
    int fg = lane >> 2, tg = lane & 3;
    float acc[8][4];
    #pragma unroll
    for (int nt = 0; nt < 8; nt++)
        #pragma unroll
        for (int c = 0; c < 4; c++) acc[nt][c] = 0.f;

    #pragma unroll
    for (int ks = 0; ks < 2; ks++){
        int kb = (ks << 4) + (tg << 1);
        uint32_t af0, af1, af2, af3;
        {
            const __half* p = sS + ((warp << 4) + fg) * MROW + kb;
            af0 = lds32h(p);
            af1 = lds32h(p + 8 * MROW);
            af2 = lds32h(p + 8);
            af3 = lds32h(p + 8 * MROW + 8);
        }
        #pragma unroll
        for (int nt = 0; nt < 8; nt++){
            const __half* p = h1T + ((nt << 3) + fg) * MROW + kb;
            uint32_t b0 = lds32h(p);
            uint32_t b1 = lds32h(p + 8);
            asm volatile(
                "mma.sync.aligned.m16n8k16.row.col.f32.f16.f16.f32 "
                "{%0,%1,%2,%3}, {%4,%5,%6,%7}, {%8,%9}, {%0,%1,%2,%3};"
                : "+f"(acc[nt][0]), "+f"(acc[nt][1]),
                  "+f"(acc[nt][2]), "+f"(acc[nt][3])
                : "r"(af0), "r"(af1), "r"(af2), "r"(af3),
                  "r"(b0), "r"(b1));
        }
    }

    lsum = 0.f; lss = 0.f;
    #pragma unroll
    for (int nt = 0; nt < 8; nt++)
        #pragma unroll
        for (int c = 0; c < 4; c++){
            float v = acc[nt][c];
            lsum += v; lss += v * v;
        }
    sv = block_reduce_sum2(lsum, lss, red);
    mu  = sv.x * (1.f / 8192.f);
    var = sv.y * (1.f / 8192.f) - mu * mu;
    inv = rsqrtf(var + 1e-5f);
    long long base = (long long)bn * GB_GTOT + g * 8192;
    #pragma unroll
    for (int half = 0; half < 2; half++){
        int o = (warp << 4) + fg + half * 8;
        #pragma unroll
        for (int nt = 0; nt < 8; nt++){
            int d = (nt << 3) + (tg << 1);
            float v0 = (acc[nt][half * 2 + 0] - mu) * inv; v0 = v0 > 0.f ? v0 : 0.f;
            float v1 = (acc[nt][half * 2 + 1] - mu) * inv; v1 = v1 > 0.f ? v1 : 0.f;
            *(__half2*)&Hh[base + o * 64 + d] = __floats2half2_rn(v0, v1);
        }
    }
}

// ---------------- split-K reduce + residual + LN1 affine ----------------
__global__ __launch_bounds__(256) void k_final(const float* __restrict__ qf,
                                               const float* __restrict__ op_b,
                                               const float* __restrict__ ln_g,
                                               const float* __restrict__ ln_b,
                                               const float* __restrict__ partial,
                                               float* __restrict__ out)
{
    __shared__ float red[18];
    int bn = blockIdx.x, j = threadIdx.x;
    float x = qf[(long long)bn * 256 + j] + op_b[j];
    #pragma unroll
    for (int sk = 0; sk < 32; sk++)
        x += partial[((long long)sk * GB_BN + bn) * 256 + j];
    float2 sv = block_reduce_sum2(x, x * x, red);
    float mu  = sv.x * (1.f / 256.f);
    float var = sv.y * (1.f / 256.f) - mu * mu;
    float inv = rsqrtf(var + 1e-5f);
    out[(long long)bn * 256 + j] = fmaf((x - mu) * inv, ln_g[j], ln_b[j]);
}

// ---------------- launcher ----------------
extern "C" void kernel_launch(void* const* d_in, const int* in_sizes, int n_in,
                              void* d_out, int out_size)
{
    (void)in_sizes; (void)n_in; (void)out_size;
    const float* feat[4];
    for (int i = 0; i < 4; i++) feat[i] = (const float*)d_in[i];
    const float* qf    = (const float*)d_in[4];
    const float* roi   = (const float*)d_in[5];
    const float* off_w = (const float*)d_in[6];
    const float* off_b = (const float*)d_in[7];
    const float* pg_w  = (const float*)d_in[8];
    const float* pg_b  = (const float*)d_in[9];
    const float* op_w  = (const float*)d_in[10];
    const float* op_b  = (const float*)d_in[11];
    const float* ln_g  = (const float*)d_in[12];
    const float* ln_b  = (const float*)d_in[13];

    float *sampled, *partial;
    __half *featTh, *paramsh, *Hh, *qfh, *pgwh, *opwh;
    cudaGetSymbolAddress((void**)&featTh,  g_featTh);
    cudaGetSymbolAddress((void**)&sampled, g_sampled);
    cudaGetSymbolAddress((void**)&paramsh, g_paramsh);
    cudaGetSymbolAddress((void**)&partial, g_partial);
    cudaGetSymbolAddress((void**)&Hh,      g_Hh);
    cudaGetSymbolAddress((void**)&qfh,     g_qfh);
    cudaGetSymbolAddress((void**)&pgwh,    g_pgwh);
    cudaGetSymbolAddress((void**)&opwh,    g_opwh);

    const int LHW[4] = {16000, 4000, 1000, 260};
    const long long LOFF[4] = {0, 16384000, 20480000, 21504000};
    for (int l = 0; l < 4; l++)
        k_transpose<<<dim3(16, (LHW[l] + 63) / 64), 256>>>(feat[l], featTh + LOFF[l], LHW[l]);

    // conversions
    k_half<<<(307200 + 255) / 256, 256>>>(qf, qfh, 307200);
    k_tconv<<<dim3(1024, 8),  256>>>(pg_w, pgwh, 256, 32768);   // -> [32768][256]
    k_tconv<<<dim3(8, 1024),  256>>>(op_w, opwh, 32768, 256);   // -> [256][32768]

    k_sample<<<GB_BN, 256>>>(qf, roi, off_w, off_b, featTh, sampled);

    // GEMM1: params(1200x32768, fp16) = qf(1200x256) @ pg_w
    k_mma_gemm<__half><<<dim3(256, 10, 1), 256>>>(
        qfh, 256, pgwh, 256,
        paramsh, 32768, 0LL, GB_BN, 256, pg_b);

    k_mix<<<GB_BN * 4, 256>>>(paramsh, sampled, Hh);

    // GEMM2: partial[z](1200x256, fp32) = H(1200x32768)[k-chunk z] @ op_w
    k_mma_gemm<float><<<dim3(2, 10, 32), 256>>>(
        Hh, 32768, opwh, 32768,
        partial, 256, 307200LL, GB_BN, 1024, (const float*)nullptr);

    k_final<<<GB_BN, 256>>>(qf, op_b, ln_g, ln_b, partial, (float*)d_out);
}

// round 16
// speedup vs baseline: 1.1739x; 1.0356x over previous
#include <cuda_runtime.h>
#include <cuda_fp16.h>
#include <cstdint>

// ---------------- problem constants ----------------
#define GB_BN   1200
#define GB_NQ   300
#define GB_GTOT 32768

// ---------------- device scratch (static, allocation-free) ----------------
__device__ __align__(16) __half g_featTh[21770240];              // fp16 pyramid
__device__ __align__(16) float g_sampled[9830400];
__device__ __align__(16) __half g_paramsh[39321600];             // params (fp16)
__device__ __align__(16) __half g_Hh[39321600];                  // H (fp16)
__device__ __align__(16) float g_partial[9830400];
__device__ __align__(16) __half g_qfh[307200];
__device__ __align__(16) __half g_pgwh[8388608];                 // pg_w^T
__device__ __align__(16) __half g_opwh[8388608];                 // op_w^T

// ---------------- block-wide sum + sumsq reduce ----------------
__device__ __forceinline__ float2 block_reduce_sum2(float s, float ss, float* red){
    #pragma unroll
    for (int o = 16; o > 0; o >>= 1){
        s  += __shfl_down_sync(0xffffffffu, s,  o);
        ss += __shfl_down_sync(0xffffffffu, ss, o);
    }
    int w = threadIdx.x >> 5;
    if ((threadIdx.x & 31) == 0){ red[w] = s; red[8 + w] = ss; }
    __syncthreads();
    if (threadIdx.x == 0){
        float a = 0.f, b = 0.f;
        #pragma unroll
        for (int i = 0; i < 8; i++){ a += red[i]; b += red[8 + i]; }
        red[16] = a; red[17] = b;
    }
    __syncthreads();
    float2 r = make_float2(red[16], red[17]);
    __syncthreads();
    return r;
}

// ---------------- feat transpose: (B,D,H,W) fp32 -> (B,G,HW,CG) fp16 ----------
__global__ __launch_bounds__(256) void k_transpose(const float* __restrict__ src,
                                                   __half* __restrict__ dst, int HW)
{
    __shared__ float tile[64][65];
    int bg = blockIdx.x;
    int b = bg >> 2, g = bg & 3;
    int s0 = blockIdx.y * 64;
    int tc = threadIdx.x & 63, tr = threadIdx.x >> 6;
    const float* sp = src + ((long long)b * 256 + g * 64) * HW;
    #pragma unroll
    for (int i = 0; i < 16; i++){
        int c = i * 4 + tr;
        int s = s0 + tc;
        tile[c][tc] = (s < HW) ? sp[(long long)c * HW + s] : 0.f;
    }
    __syncthreads();
    __half* dp = dst + (long long)(b * 4 + g) * HW * 64;
    #pragma unroll
    for (int i = 0; i < 16; i++){
        int sl = i * 4 + tr;
        int s = s0 + sl;
        if (s < HW) dp[(long long)s * 64 + tc] = __float2half_rn(tile[tc][sl]);
    }
}

// ---------------- offsets + level softmax + bilinear gather (fp16 feat) -------
__global__ __launch_bounds__(256) void k_sample(const float* __restrict__ qf,
                                                const float* __restrict__ roi,
                                                const float* __restrict__ off_w,
                                                const float* __restrict__ off_b,
                                                const __half* __restrict__ featT,
                                                float* __restrict__ sampled)
{
    __shared__ float s_qf[256];
    __shared__ float s_pt[128][6];
    int bn = blockIdx.x;
    int b  = bn / GB_NQ;
    int tid = threadIdx.x;
    s_qf[tid] = qf[(long long)bn * 256 + tid];
    __syncthreads();

    if (tid < 128){
        const float* wp = off_w + tid * 3;
        float o0 = off_b[tid * 3 + 0];
        float o1 = off_b[tid * 3 + 1];
        float o2 = off_b[tid * 3 + 2];
        #pragma unroll 8
        for (int k = 0; k < 256; k++){
            float q = s_qf[k];
            o0 = fmaf(q, wp[(long long)k * 384 + 0], o0);
            o1 = fmaf(q, wp[(long long)k * 384 + 1], o1);
            o2 = fmaf(q, wp[(long long)k * 384 + 2], o2);
        }
        float cx = roi[bn * 4 + 0], cy = roi[bn * 4 + 1];
        float z  = roi[bn * 4 + 2], rr = roi[bn * 4 + 3];
        float sc = exp2f(z);
        float rw = sc * exp2f(-0.5f * rr);
        float rh = sc * exp2f( 0.5f * rr);
        float sx = fmaf(o0, rw, cx);
        float sy = fmaf(o1, rh, cy);
        float t  = z + o2 - 3.0f;
        float e0 = expf(-0.5f * t * t);
        float e1 = expf(-0.5f * (t - 1.f) * (t - 1.f));
        float e2 = expf(-0.5f * (t - 2.f) * (t - 2.f));
        float e3 = expf(-0.5f * (t - 3.f) * (t - 3.f));
        float inv = 1.f / (e0 + e1 + e2 + e3);
        s_pt[tid][0] = sx; s_pt[tid][1] = sy;
        s_pt[tid][2] = e0 * inv; s_pt[tid][3] = e1 * inv;
        s_pt[tid][4] = e2 * inv; s_pt[tid][5] = e3 * inv;
    }
    __syncthreads();

    const int   LHh[4]  = {100, 50, 25, 13};
    const int   LWw[4]  = {160, 80, 40, 20};
    const int   LHW[4]  = {16000, 4000, 1000, 260};
    const float LIS[4]  = {0.125f, 0.0625f, 0.03125f, 0.015625f};
    const long long LOFF[4] = {0, 16384000, 20480000, 21504000};

    int c4 = tid & 15;
    #pragma unroll
    for (int it = 0; it < 8; it++){
        int pt = it * 16 + (tid >> 4);
        int g  = pt >> 5;
        float sx = s_pt[pt][0], sy = s_pt[pt][1];
        float4 acc = make_float4(0.f, 0.f, 0.f, 0.f);
        #pragma unroll
        for (int l = 0; l < 4; l++){
            float lw = s_pt[pt][2 + l];
            int W = LWw[l], H = LHh[l];
            const __half* fp = featT + LOFF[l] + (long long)(b * 4 + g) * LHW[l] * 64;
            float px = fmaf(sx, LIS[l], -0.5f);
            float py = fmaf(sy, LIS[l], -0.5f);
            float x0f = floorf(px), y0f = floorf(py);
            int x0 = (int)x0f, y0 = (int)y0f;
            float wx = px - x0f, wy = py - y0f;
            float w00 = (1.f - wx) * (1.f - wy);
            float w10 = wx * (1.f - wy);
            float w01 = (1.f - wx) * wy;
            float w11 = wx * wy;
            auto corner = [&](int xi, int yi, float cw){
                if (xi >= 0 && xi < W && yi >= 0 && yi < H){
                    const __half2* hp = (const __half2*)(fp + ((long long)yi * W + xi) * 64 + c4 * 4);
                    float2 f01 = __half22float2(hp[0]);
                    float2 f23 = __half22float2(hp[1]);
                    float ww = lw * cw;
                    acc.x = fmaf(ww, f01.x, acc.x);
                    acc.y = fmaf(ww, f01.y, acc.y);
                    acc.z = fmaf(ww, f23.x, acc.z);
                    acc.w = fmaf(ww, f23.y, acc.w);
                }
            };
            corner(x0,     y0,     w00);
            corner(x0 + 1, y0,     w10);
            corner(x0,     y0 + 1, w01);
            corner(x0 + 1, y0 + 1, w11);
        }
        *(float4*)(sampled + ((long long)bn * 128 + pt) * 64 + c4 * 4) = acc;
    }
}

// ---------------- fp32 -> fp16 elementwise ----------------
__global__ __launch_bounds__(256) void k_half(const float* __restrict__ in,
                                              __half* __restrict__ hi, int n)
{
    int i = blockIdx.x * 256 + threadIdx.x;
    if (i < n) hi[i] = __float2half_rn(in[i]);
}

// ---------------- transpose + fp16: in[R][C] -> out[C][R] ----------------
__global__ __launch_bounds__(256) void k_tconv(const float* __restrict__ in,
                                               __half* __restrict__ ohi,
                                               int R, int C)
{
    __shared__ float t[32][33];
    int c0 = blockIdx.x * 32, r0 = blockIdx.y * 32;
    int tx = threadIdx.x & 31, ty = threadIdx.x >> 5;
    #pragma unroll
    for (int i = 0; i < 4; i++){
        int r = r0 + ty + i * 8;
        t[ty + i * 8][tx] = in[(size_t)r * C + c0 + tx];
    }
    __syncthreads();
    #pragma unroll
    for (int i = 0; i < 4; i++){
        int c = c0 + ty + i * 8;
        ohi[(size_t)c * R + r0 + tx] = __float2half_rn(t[tx][ty + i * 8]);
    }
}

// ---------------- GEMM via mma.sync fp16, BK=32 (proven) ----------------------
#define SROW 40

__device__ __forceinline__ uint32_t lds32h(const __half* p){
    return *(const uint32_t*)p;
}

template <typename CT>
__global__ __launch_bounds__(256) void k_mma_gemm(
    const __half* __restrict__ A, int lda,
    const __half* __restrict__ B, int ldb,
    CT* __restrict__ C, int ldc, long long zstride,
    int Mrows, int ksplit, const float* __restrict__ bias)
{
    __shared__ __half sA[128 * SROW];
    __shared__ __half sB[128 * SROW];

    int tid = threadIdx.x;
    int warp = tid >> 5, lane = tid & 31;
    int g = lane >> 2, tg = lane & 3;
    int wm = warp & 1, wn = warp >> 1;
    int m0 = blockIdx.y * 128;
    int n0 = blockIdx.x * 128;
    int kbase = blockIdx.z * ksplit;
    C += (long long)blockIdx.z * zstride;

    float acc[4][4][4];
    #pragma unroll
    for (int a = 0; a < 4; a++)
        #pragma unroll
        for (int b = 0; b < 4; b++)
            #pragma unroll
            for (int c = 0; c < 4; c++) acc[a][b][c] = 0.f;

    int NK = ksplit >> 5;
    for (int kc = 0; kc < NK; kc++){
        int k0 = kbase + (kc << 5);
        #pragma unroll
        for (int t = 0; t < 2; t++){
            int idx = tid + t * 256;
            int r = idx >> 2, c8 = (idx & 3) << 3;
            int m = m0 + r;
            uint4 va = make_uint4(0u,0u,0u,0u);
            if (m < Mrows) va = *(const uint4*)(A + (size_t)m * lda + k0 + c8);
            *(uint4*)&sA[r * SROW + c8] = va;
            size_t gb = (size_t)(n0 + r) * ldb + k0 + c8;
            *(uint4*)&sB[r * SROW + c8] = *(const uint4*)(B + gb);
        }
        __syncthreads();

        #pragma unroll
        for (int ks = 0; ks < 2; ks++){
            int kb = (ks << 4) + (tg << 1);
            uint32_t af[4][4];
            #pragma unroll
            for (int mt = 0; mt < 4; mt++){
                const __half* p = sA + ((wm << 6) + (mt << 4) + g) * SROW + kb;
                af[mt][0] = lds32h(p);
                af[mt][1] = lds32h(p + 8 * SROW);
                af[mt][2] = lds32h(p + 8);
                af[mt][3] = lds32h(p + 8 * SROW + 8);
            }
            #pragma unroll
            for (int nt = 0; nt < 4; nt++){
                const __half* p = sB + ((wn << 5) + (nt << 3) + g) * SROW + kb;
                uint32_t b0 = lds32h(p);
                uint32_t b1 = lds32h(p + 8);
                #pragma unroll
                for (int mt = 0; mt < 4; mt++){
                    asm volatile(
                        "mma.sync.aligned.m16n8k16.row.col.f32.f16.f16.f32 "
                        "{%0,%1,%2,%3}, {%4,%5,%6,%7}, {%8,%9}, {%0,%1,%2,%3};"
                        : "+f"(acc[mt][nt][0]), "+f"(acc[mt][nt][1]),
                          "+f"(acc[mt][nt][2]), "+f"(acc[mt][nt][3])
                        : "r"(af[mt][0]), "r"(af[mt][1]), "r"(af[mt][2]), "r"(af[mt][3]),
                          "r"(b0), "r"(b1));
                }
            }
        }
        __syncthreads();
    }

    #pragma unroll
    for (int mt = 0; mt < 4; mt++){
        #pragma unroll
        for (int half = 0; half < 2; half++){
            int m = m0 + (wm << 6) + (mt << 4) + g + half * 8;
            if (m < Mrows){
                CT* cp = C + (size_t)m * ldc + n0 + (wn << 5) + (tg << 1);
                #pragma unroll
                for (int nt = 0; nt < 4; nt++){
                    float v0 = acc[mt][nt][half * 2 + 0];
                    float v1 = acc[mt][nt][half * 2 + 1];
                    if (bias){
                        int col = n0 + (wn << 5) + (nt << 3) + (tg << 1);
                        v0 += bias[col];
                        v1 += bias[col + 1];
                    }
                    if (sizeof(CT) == 2){
                        *(__half2*)(cp + (nt << 3)) = __floats2half2_rn(v0, v1);
                    } else {
                        *(float2*)((float*)cp + (nt << 3)) = make_float2(v0, v1);
                    }
                }
            }
        }
    }
}

// ---------------- per-(b,n,g) mixing: BOTH phases HMMA ------------------------
#define MROW  40   // pad for S / h1T fp16 tiles (K=32 rows)
#define MROW1 72   // pad for sampled / M^T fp16 tiles (K=64 rows); frag banks 4fg+tg distinct

__global__ __launch_bounds__(256) void k_mix(const __half* __restrict__ params,
                                             const float* __restrict__ sampled,
                                             __half* __restrict__ Hh)
{
    __shared__ __half sS1[32 * MROW1];    // sampled fp16 [p][c]
    __shared__ __half sMT[64 * MROW1];    // M^T fp16 [d][c]
    __shared__ __half sS [128 * MROW];    // S fp16 [o][p]
    __shared__ __half h1T[64 * MROW];     // h1^T fp16 [d][p]
    __shared__ float  red[18];
    int bg = blockIdx.x;
    int bn = bg >> 2, g = bg & 3;
    int tid = threadIdx.x;
    const __half2* P2 = (const __half2*)(params + (long long)bn * GB_GTOT + g * 8192);
    const float* SP = sampled + ((long long)bn * 128 + g * 32) * 64;

    // stage sampled fp16: idx -> p = idx>>6, c = idx&63
    #pragma unroll
    for (int i = 0; i < 8; i++){
        int idx = tid + i * 256;
        sS1[(idx >> 6) * MROW1 + (idx & 63)] = __float2half_rn(SP[idx]);
    }
    // stage M^T and S from params (both already fp16)
    #pragma unroll
    for (int i = 0; i < 8; i++){
        int idx = tid + i * 256;                 // half2 index
        __half2 h2 = P2[idx];                    // M[c][d], c=idx>>5, d=2*(idx&31)
        int c = idx >> 5, d = (idx & 31) << 1;
        sMT[(d    ) * MROW1 + c] = __low2half(h2);
        sMT[(d + 1) * MROW1 + c] = __high2half(h2);
        // S[o][p], o=idx>>4, p=(idx&15)*2
        int o = idx >> 4, pp = (idx & 15) << 1;
        *(__half2*)&sS[o * MROW + pp] = P2[2048 + idx];
    }
    __syncthreads();

    int warp = tid >> 5, lane = tid & 31;
    int fg = lane >> 2, tg = lane & 3;

    // ---- phase 1: h1(32x64) = sampled @ M via HMMA ----
    // warp -> (mt, ntp): mt = warp&1 (2 m16 tiles), ntp = warp>>1 (4 pairs of n8 tiles)
    int mt1 = warp & 1, ntp = warp >> 1;
    float acc1[2][4];
    #pragma unroll
    for (int q = 0; q < 2; q++)
        #pragma unroll
        for (int c = 0; c < 4; c++) acc1[q][c] = 0.f;
    #pragma unroll
    for (int ks = 0; ks < 4; ks++){
        int kb = (ks << 4) + (tg << 1);
        uint32_t af0, af1, af2, af3;
        {
            const __half* p = sS1 + ((mt1 << 4) + fg) * MROW1 + kb;
            af0 = lds32h(p);
            af1 = lds32h(p + 8 * MROW1);
            af2 = lds32h(p + 8);
            af3 = lds32h(p + 8 * MROW1 + 8);
        }
        #pragma unroll
        for (int q = 0; q < 2; q++){
            int nt = (ntp << 1) + q;
            const __half* p = sMT + ((nt << 3) + fg) * MROW1 + kb;
            uint32_t b0 = lds32h(p);
            uint32_t b1 = lds32h(p + 8);
            asm volatile(
                "mma.sync.aligned.m16n8k16.row.col.f32.f16.f16.f32 "
                "{%0,%1,%2,%3}, {%4,%5,%6,%7}, {%8,%9}, {%0,%1,%2,%3};"
                : "+f"(acc1[q][0]), "+f"(acc1[q][1]),
                  "+f"(acc1[q][2]), "+f"(acc1[q][3])
                : "r"(af0), "r"(af1), "r"(af2), "r"(af3),
                  "r"(b0), "r"(b1));
        }
    }
    float lsum = 0.f, lss = 0.f;
    #pragma unroll
    for (int q = 0; q < 2; q++)
        #pragma unroll
        for (int c = 0; c < 4; c++){
            float v = acc1[q][c];
            lsum += v; lss += v * v;
        }
    float2 sv = block_reduce_sum2(lsum, lss, red);
    float mu  = sv.x * (1.f / 2048.f);
    float var = sv.y * (1.f / 2048.f) - mu * mu;
    float inv = rsqrtf(var + 1e-5f);
    // LN + ReLU + write h1T[d][p] fp16. D[p][d]: p = mt1*16+fg+8h, d = nt*8+tg*2+{0,1}
    #pragma unroll
    for (int q = 0; q < 2; q++){
        int nt = (ntp << 1) + q;
        #pragma unroll
        for (int half = 0; half < 2; half++){
            int p = (mt1 << 4) + fg + half * 8;
            int d = (nt << 3) + (tg << 1);
            float v0 = (acc1[q][half * 2 + 0] - mu) * inv; v0 = v0 > 0.f ? v0 : 0.f;
            float v1 = (acc1[q][half * 2 + 1] - mu) * inv; v1 = v1 > 0.f ? v1 : 0.f;
            h1T[(d    ) * MROW + p] = __float2half_rn(v0);
            h1T[(d + 1) * MROW + p] = __float2half_rn(v1);
        }
    }
    __syncthreads();

    // ---- phase 2: h2 = S @ h1 via HMMA (r13/r15 proven) ----
    float acc[8][4];
    #pragma unroll
    for (int nt = 0; nt < 8; nt++)
        #pragma unroll
        for (int c = 0; c < 4; c++) acc[nt][c] = 0.f;

    #pragma unroll
    for (int ks = 0; ks < 2; ks++){
        int kb = (ks << 4) + (tg << 1);
        uint32_t af0, af1, af2, af3;
        {
            const __half* p = sS + ((warp << 4) + fg) * MROW + kb;
            af0 = lds32h(p);
            af1 = lds32h(p + 8 * MROW);
            af2 = lds32h(p + 8);
            af3 = lds32h(p + 8 * MROW + 8);
        }
        #pragma unroll
        for (int nt = 0; nt < 8; nt++){
            const __half* p = h1T + ((nt << 3) + fg) * MROW + kb;
            uint32_t b0 = lds32h(p);
            uint32_t b1 = lds32h(p + 8);
            asm volatile(
                "mma.sync.aligned.m16n8k16.row.col.f32.f16.f16.f32 "
                "{%0,%1,%2,%3}, {%4,%5,%6,%7}, {%8,%9}, {%0,%1,%2,%3};"
                : "+f"(acc[nt][0]), "+f"(acc[nt][1]),
                  "+f"(acc[nt][2]), "+f"(acc[nt][3])
                : "r"(af0), "r"(af1), "r"(af2), "r"(af3),
                  "r"(b0), "r"(b1));
        }
    }

    lsum = 0.f; lss = 0.f;
    #pragma unroll
    for (int nt = 0; nt < 8; nt++)
        #pragma unroll
        for (int c = 0; c < 4; c++){
            float v = acc[nt][c];
            lsum += v; lss += v * v;
        }
    sv = block_reduce_sum2(lsum, lss, red);
    mu  = sv.x * (1.f / 8192.f);
    var = sv.y * (1.f / 8192.f) - mu * mu;
    inv = rsqrtf(var + 1e-5f);
    long long base = (long long)bn * GB_GTOT + g * 8192;
    #pragma unroll
    for (int half = 0; half < 2; half++){
        int o = (warp << 4) + fg + half * 8;
        #pragma unroll
        for (int nt = 0; nt < 8; nt++){
            int d = (nt << 3) + (tg << 1);
            float v0 = (acc[nt][half * 2 + 0] - mu) * inv; v0 = v0 > 0.f ? v0 : 0.f;
            float v1 = (acc[nt][half * 2 + 1] - mu) * inv; v1 = v1 > 0.f ? v1 : 0.f;
            *(__half2*)&Hh[base + o * 64 + d] = __floats2half2_rn(v0, v1);
        }
    }
}

// ---------------- split-K reduce + residual + LN1 affine ----------------
__global__ __launch_bounds__(256) void k_final(const float* __restrict__ qf,
                                               const float* __restrict__ op_b,
                                               const float* __restrict__ ln_g,
                                               const float* __restrict__ ln_b,
                                               const float* __restrict__ partial,
                                               float* __restrict__ out)
{
    __shared__ float red[18];
    int bn = blockIdx.x, j = threadIdx.x;
    float x = qf[(long long)bn * 256 + j] + op_b[j];
    #pragma unroll
    for (int sk = 0; sk < 32; sk++)
        x += partial[((long long)sk * GB_BN + bn) * 256 + j];
    float2 sv = block_reduce_sum2(x, x * x, red);
    float mu  = sv.x * (1.f / 256.f);
    float var = sv.y * (1.f / 256.f) - mu * mu;
    float inv = rsqrtf(var + 1e-5f);
    out[(long long)bn * 256 + j] = fmaf((x - mu) * inv, ln_g[j], ln_b[j]);
}

// ---------------- launcher ----------------
extern "C" void kernel_launch(void* const* d_in, const int* in_sizes, int n_in,
                              void* d_out, int out_size)
{
    (void)in_sizes; (void)n_in; (void)out_size;
    const float* feat[4];
    for (int i = 0; i < 4; i++) feat[i] = (const float*)d_in[i];
    const float* qf    = (const float*)d_in[4];
    const float* roi   = (const float*)d_in[5];
    const float* off_w = (const float*)d_in[6];
    const float* off_b = (const float*)d_in[7];
    const float* pg_w  = (const float*)d_in[8];
    const float* pg_b  = (const float*)d_in[9];
    const float* op_w  = (const float*)d_in[10];
    const float* op_b  = (const float*)d_in[11];
    const float* ln_g  = (const float*)d_in[12];
    const float* ln_b  = (const float*)d_in[13];

    float *sampled, *partial;
    __half *featTh, *paramsh, *Hh, *qfh, *pgwh, *opwh;
    cudaGetSymbolAddress((void**)&featTh,  g_featTh);
    cudaGetSymbolAddress((void**)&sampled, g_sampled);
    cudaGetSymbolAddress((void**)&paramsh, g_paramsh);
    cudaGetSymbolAddress((void**)&partial, g_partial);
    cudaGetSymbolAddress((void**)&Hh,      g_Hh);
    cudaGetSymbolAddress((void**)&qfh,     g_qfh);
    cudaGetSymbolAddress((void**)&pgwh,    g_pgwh);
    cudaGetSymbolAddress((void**)&opwh,    g_opwh);

    const int LHW[4] = {16000, 4000, 1000, 260};
    const long long LOFF[4] = {0, 16384000, 20480000, 21504000};
    for (int l = 0; l < 4; l++)
        k_transpose<<<dim3(16, (LHW[l] + 63) / 64), 256>>>(feat[l], featTh + LOFF[l], LHW[l]);

    // conversions
    k_half<<<(307200 + 255) / 256, 256>>>(qf, qfh, 307200);
    k_tconv<<<dim3(1024, 8),  256>>>(pg_w, pgwh, 256, 32768);   // -> [32768][256]
    k_tconv<<<dim3(8, 1024),  256>>>(op_w, opwh, 32768, 256);   // -> [256][32768]

    k_sample<<<GB_BN, 256>>>(qf, roi, off_w, off_b, featTh, sampled);

    // GEMM1: params(1200x32768, fp16) = qf(1200x256) @ pg_w
    k_mma_gemm<__half><<<dim3(256, 10, 1), 256>>>(
        qfh, 256, pgwh, 256,
        paramsh, 32768, 0LL, GB_BN, 256, pg_b);

    k_mix<<<GB_BN * 4, 256>>>(paramsh, sampled, Hh);

    // GEMM2: partial[z](1200x256, fp32) = H(1200x32768)[k-chunk z] @ op_w
    k_mma_gemm<float><<<dim3(2, 10, 32), 256>>>(
        Hh, 32768, opwh, 32768,
        partial, 256, 307200LL, GB_BN, 1024, (const float*)nullptr);

    k_final<<<GB_BN, 256>>>(qf, op_b, ln_g, ln_b, partial, (float*)d_out);
}

// round 17
// speedup vs baseline: 1.2625x; 1.0755x over previous
#include <cuda_runtime.h>
#include <cuda_fp16.h>
#include <cstdint>

// ---------------- problem constants ----------------
#define GB_BN   1200
#define GB_NQ   300
#define GB_GTOT 32768

// ---------------- device scratch (static, allocation-free) ----------------
__device__ __align__(16) __half g_featTh[21770240];              // fp16 pyramid
__device__ __align__(16) __half g_sampledh[9830400];             // sampled (fp16)
__device__ __align__(16) __half g_paramsh[39321600];             // params (fp16)
__device__ __align__(16) __half g_Hh[39321600];                  // H (fp16)
__device__ __align__(16) float g_partial[9830400];
__device__ __align__(16) float g_offs[460800];                   // offsets (1200x384 fp32)
__device__ __align__(16) __half g_qfh[307200];
__device__ __align__(16) __half g_pgwh[8388608];                 // pg_w^T
__device__ __align__(16) __half g_opwh[8388608];                 // op_w^T
__device__ __align__(16) __half g_offwh[98304];                  // off_w^T (384x256)

// ---------------- block-wide sum + sumsq reduce ----------------
__device__ __forceinline__ float2 block_reduce_sum2(float s, float ss, float* red){
    #pragma unroll
    for (int o = 16; o > 0; o >>= 1){
        s  += __shfl_down_sync(0xffffffffu, s,  o);
        ss += __shfl_down_sync(0xffffffffu, ss, o);
    }
    int w = threadIdx.x >> 5;
    if ((threadIdx.x & 31) == 0){ red[w] = s; red[8 + w] = ss; }
    __syncthreads();
    if (threadIdx.x == 0){
        float a = 0.f, b = 0.f;
        #pragma unroll
        for (int i = 0; i < 8; i++){ a += red[i]; b += red[8 + i]; }
        red[16] = a; red[17] = b;
    }
    __syncthreads();
    float2 r = make_float2(red[16], red[17]);
    __syncthreads();
    return r;
}

// ---------------- feat transpose: (B,D,H,W) fp32 -> (B,G,HW,CG) fp16 ----------
__global__ __launch_bounds__(256) void k_transpose(const float* __restrict__ src,
                                                   __half* __restrict__ dst, int HW)
{
    __shared__ float tile[64][65];
    int bg = blockIdx.x;
    int b = bg >> 2, g = bg & 3;
    int s0 = blockIdx.y * 64;
    int tc = threadIdx.x & 63, tr = threadIdx.x >> 6;
    const float* sp = src + ((long long)b * 256 + g * 64) * HW;
    #pragma unroll
    for (int i = 0; i < 16; i++){
        int c = i * 4 + tr;
        int s = s0 + tc;
        tile[c][tc] = (s < HW) ? sp[(long long)c * HW + s] : 0.f;
    }
    __syncthreads();
    __half* dp = dst + (long long)(b * 4 + g) * HW * 64;
    #pragma unroll
    for (int i = 0; i < 16; i++){
        int sl = i * 4 + tr;
        int s = s0 + sl;
        if (s < HW) dp[(long long)s * 64 + tc] = __float2half_rn(tile[tc][sl]);
    }
}

// ---------------- level softmax + bilinear gather (offsets precomputed) -------
__global__ __launch_bounds__(256) void k_sample(const float* __restrict__ offs,
                                                const float* __restrict__ roi,
                                                const __half* __restrict__ featT,
                                                __half* __restrict__ sampled)
{
    __shared__ float s_pt[128][6];
    int bn = blockIdx.x;
    int b  = bn / GB_NQ;
    int tid = threadIdx.x;

    if (tid < 128){
        float o0 = offs[(long long)bn * 384 + tid * 3 + 0];
        float o1 = offs[(long long)bn * 384 + tid * 3 + 1];
        float o2 = offs[(long long)bn * 384 + tid * 3 + 2];
        float cx = roi[bn * 4 + 0], cy = roi[bn * 4 + 1];
        float z  = roi[bn * 4 + 2], rr = roi[bn * 4 + 3];
        float sc = exp2f(z);
        float rw = sc * exp2f(-0.5f * rr);
        float rh = sc * exp2f( 0.5f * rr);
        float sx = fmaf(o0, rw, cx);
        float sy = fmaf(o1, rh, cy);
        float t  = z + o2 - 3.0f;
        float e0 = expf(-0.5f * t * t);
        float e1 = expf(-0.5f * (t - 1.f) * (t - 1.f));
        float e2 = expf(-0.5f * (t - 2.f) * (t - 2.f));
        float e3 = expf(-0.5f * (t - 3.f) * (t - 3.f));
        float inv = 1.f / (e0 + e1 + e2 + e3);
        s_pt[tid][0] = sx; s_pt[tid][1] = sy;
        s_pt[tid][2] = e0 * inv; s_pt[tid][3] = e1 * inv;
        s_pt[tid][4] = e2 * inv; s_pt[tid][5] = e3 * inv;
    }
    __syncthreads();

    const int   LHh[4]  = {100, 50, 25, 13};
    const int   LWw[4]  = {160, 80, 40, 20};
    const int   LHW[4]  = {16000, 4000, 1000, 260};
    const float LIS[4]  = {0.125f, 0.0625f, 0.03125f, 0.015625f};
    const long long LOFF[4] = {0, 16384000, 20480000, 21504000};

    int c4 = tid & 15;
    #pragma unroll
    for (int it = 0; it < 8; it++){
        int pt = it * 16 + (tid >> 4);
        int g  = pt >> 5;
        float sx = s_pt[pt][0], sy = s_pt[pt][1];
        float4 acc = make_float4(0.f, 0.f, 0.f, 0.f);
        #pragma unroll
        for (int l = 0; l < 4; l++){
            float lw = s_pt[pt][2 + l];
            int W = LWw[l], H = LHh[l];
            const __half* fp = featT + LOFF[l] + (long long)(b * 4 + g) * LHW[l] * 64;
            float px = fmaf(sx, LIS[l], -0.5f);
            float py = fmaf(sy, LIS[l], -0.5f);
            float x0f = floorf(px), y0f = floorf(py);
            int x0 = (int)x0f, y0 = (int)y0f;
            float wx = px - x0f, wy = py - y0f;
            float w00 = (1.f - wx) * (1.f - wy);
            float w10 = wx * (1.f - wy);
            float w01 = (1.f - wx) * wy;
            float w11 = wx * wy;
            auto corner = [&](int xi, int yi, float cw){
                if (xi >= 0 && xi < W && yi >= 0 && yi < H){
                    const __half2* hp = (const __half2*)(fp + ((long long)yi * W + xi) * 64 + c4 * 4);
                    float2 f01 = __half22float2(hp[0]);
                    float2 f23 = __half22float2(hp[1]);
                    float ww = lw * cw;
                    acc.x = fmaf(ww, f01.x, acc.x);
                    acc.y = fmaf(ww, f01.y, acc.y);
                    acc.z = fmaf(ww, f23.x, acc.z);
                    acc.w = fmaf(ww, f23.y, acc.w);
                }
            };
            corner(x0,     y0,     w00);
            corner(x0 + 1, y0,     w10);
            corner(x0,     y0 + 1, w01);
            corner(x0 + 1, y0 + 1, w11);
        }
        __half* op = sampled + ((long long)bn * 128 + pt) * 64 + c4 * 4;
        *(__half2*)(op)     = __floats2half2_rn(acc.x, acc.y);
        *(__half2*)(op + 2) = __floats2half2_rn(acc.z, acc.w);
    }
}

// ---------------- fp32 -> fp16 elementwise ----------------
__global__ __launch_bounds__(256) void k_half(const float* __restrict__ in,
                                              __half* __restrict__ hi, int n)
{
    int i = blockIdx.x * 256 + threadIdx.x;
    if (i < n) hi[i] = __float2half_rn(in[i]);
}

// ---------------- transpose + fp16: in[R][C] -> out[C][R] ----------------
__global__ __launch_bounds__(256) void k_tconv(const float* __restrict__ in,
                                               __half* __restrict__ ohi,
                                               int R, int C)
{
    __shared__ float t[32][33];
    int c0 = blockIdx.x * 32, r0 = blockIdx.y * 32;
    int tx = threadIdx.x & 31, ty = threadIdx.x >> 5;
    #pragma unroll
    for (int i = 0; i < 4; i++){
        int r = r0 + ty + i * 8;
        t[ty + i * 8][tx] = in[(size_t)r * C + c0 + tx];
    }
    __syncthreads();
    #pragma unroll
    for (int i = 0; i < 4; i++){
        int c = c0 + ty + i * 8;
        ohi[(size_t)c * R + r0 + tx] = __float2half_rn(t[tx][ty + i * 8]);
    }
}

// ---------------- GEMM via mma.sync fp16, BK=32 (proven) ----------------------
#define SROW 40

__device__ __forceinline__ uint32_t lds32h(const __half* p){
    return *(const uint32_t*)p;
}

template <typename CT>
__global__ __launch_bounds__(256) void k_mma_gemm(
    const __half* __restrict__ A, int lda,
    const __half* __restrict__ B, int ldb,
    CT* __restrict__ C, int ldc, long long zstride,
    int Mrows, int ksplit, const float* __restrict__ bias)
{
    __shared__ __half sA[128 * SROW];
    __shared__ __half sB[128 * SROW];

    int tid = threadIdx.x;
    int warp = tid >> 5, lane = tid & 31;
    int g = lane >> 2, tg = lane & 3;
    int wm = warp & 1, wn = warp >> 1;
    int m0 = blockIdx.y * 128;
    int n0 = blockIdx.x * 128;
    int kbase = blockIdx.z * ksplit;
    C += (long long)blockIdx.z * zstride;

    float acc[4][4][4];
    #pragma unroll
    for (int a = 0; a < 4; a++)
        #pragma unroll
        for (int b = 0; b < 4; b++)
            #pragma unroll
            for (int c = 0; c < 4; c++) acc[a][b][c] = 0.f;

    int NK = ksplit >> 5;
    for (int kc = 0; kc < NK; kc++){
        int k0 = kbase + (kc << 5);
        #pragma unroll
        for (int t = 0; t < 2; t++){
            int idx = tid + t * 256;
            int r = idx >> 2, c8 = (idx & 3) << 3;
            int m = m0 + r;
            uint4 va = make_uint4(0u,0u,0u,0u);
            if (m < Mrows) va = *(const uint4*)(A + (size_t)m * lda + k0 + c8);
            *(uint4*)&sA[r * SROW + c8] = va;
            size_t gb = (size_t)(n0 + r) * ldb + k0 + c8;
            *(uint4*)&sB[r * SROW + c8] = *(const uint4*)(B + gb);
        }
        __syncthreads();

        #pragma unroll
        for (int ks = 0; ks < 2; ks++){
            int kb = (ks << 4) + (tg << 1);
            uint32_t af[4][4];
            #pragma unroll
            for (int mt = 0; mt < 4; mt++){
                const __half* p = sA + ((wm << 6) + (mt << 4) + g) * SROW + kb;
                af[mt][0] = lds32h(p);
                af[mt][1] = lds32h(p + 8 * SROW);
                af[mt][2] = lds32h(p + 8);
                af[mt][3] = lds32h(p + 8 * SROW + 8);
            }
            #pragma unroll
            for (int nt = 0; nt < 4; nt++){
                const __half* p = sB + ((wn << 5) + (nt << 3) + g) * SROW + kb;
                uint32_t b0 = lds32h(p);
                uint32_t b1 = lds32h(p + 8);
                #pragma unroll
                for (int mt = 0; mt < 4; mt++){
                    asm volatile(
                        "mma.sync.aligned.m16n8k16.row.col.f32.f16.f16.f32 "
                        "{%0,%1,%2,%3}, {%4,%5,%6,%7}, {%8,%9}, {%0,%1,%2,%3};"
                        : "+f"(acc[mt][nt][0]), "+f"(acc[mt][nt][1]),
                          "+f"(acc[mt][nt][2]), "+f"(acc[mt][nt][3])
                        : "r"(af[mt][0]), "r"(af[mt][1]), "r"(af[mt][2]), "r"(af[mt][3]),
                          "r"(b0), "r"(b1));
                }
            }
        }
        __syncthreads();
    }

    #pragma unroll
    for (int mt = 0; mt < 4; mt++){
        #pragma unroll
        for (int half = 0; half < 2; half++){
            int m = m0 + (wm << 6) + (mt << 4) + g + half * 8;
            if (m < Mrows){
                CT* cp = C + (size_t)m * ldc + n0 + (wn << 5) + (tg << 1);
                #pragma unroll
                for (int nt = 0; nt < 4; nt++){
                    float v0 = acc[mt][nt][half * 2 + 0];
                    float v1 = acc[mt][nt][half * 2 + 1];
                    if (bias){
                        int col = n0 + (wn << 5) + (nt << 3) + (tg << 1);
                        v0 += bias[col];
                        v1 += bias[col + 1];
                    }
                    if (sizeof(CT) == 2){
                        *(__half2*)(cp + (nt << 3)) = __floats2half2_rn(v0, v1);
                    } else {
                        *(float2*)((float*)cp + (nt << 3)) = make_float2(v0, v1);
                    }
                }
            }
        }
    }
}

// ---------------- per-(b,n,g) mixing: BOTH phases HMMA (r16 proven) -----------
#define MROW  40
#define MROW1 72

__global__ __launch_bounds__(256) void k_mix(const __half* __restrict__ params,
                                             const __half* __restrict__ sampled,
                                             __half* __restrict__ Hh)
{
    __shared__ __half sS1[32 * MROW1];    // sampled fp16 [p][c]
    __shared__ __half sMT[64 * MROW1];    // M^T fp16 [d][c]
    __shared__ __half sS [128 * MROW];    // S fp16 [o][p]
    __shared__ __half h1T[64 * MROW];     // h1^T fp16 [d][p]
    __shared__ float  red[18];
    int bg = blockIdx.x;
    int bn = bg >> 2, g = bg & 3;
    int tid = threadIdx.x;
    const __half2* P2 = (const __half2*)(params + (long long)bn * GB_GTOT + g * 8192);
    const __half2* SP2 = (const __half2*)(sampled + ((long long)bn * 128 + g * 32) * 64);

    // stage sampled fp16 (already half): half2 idx -> p = idx>>5, c = (idx&31)*2
    #pragma unroll
    for (int i = 0; i < 4; i++){
        int idx = tid + i * 256;
        int p = idx >> 5, c = (idx & 31) << 1;
        *(__half2*)&sS1[p * MROW1 + c] = SP2[idx];
    }
    // stage M^T and S from params
    #pragma unroll
    for (int i = 0; i < 8; i++){
        int idx = tid + i * 256;
        __half2 h2 = P2[idx];                    // M[c][d], c=idx>>5, d=2*(idx&31)
        int c = idx >> 5, d = (idx & 31) << 1;
        sMT[(d    ) * MROW1 + c] = __low2half(h2);
        sMT[(d + 1) * MROW1 + c] = __high2half(h2);
        int o = idx >> 4, pp = (idx & 15) << 1;
        *(__half2*)&sS[o * MROW + pp] = P2[2048 + idx];
    }
    __syncthreads();

    int warp = tid >> 5, lane = tid & 31;
    int fg = lane >> 2, tg = lane & 3;

    // ---- phase 1: h1(32x64) = sampled @ M via HMMA ----
    int mt1 = warp & 1, ntp = warp >> 1;
    float acc1[2][4];
    #pragma unroll
    for (int q = 0; q < 2; q++)
        #pragma unroll
        for (int c = 0; c < 4; c++) acc1[q][c] = 0.f;
    #pragma unroll
    for (int ks = 0; ks < 4; ks++){
        int kb = (ks << 4) + (tg << 1);
        uint32_t af0, af1, af2, af3;
        {
            const __half* p = sS1 + ((mt1 << 4) + fg) * MROW1 + kb;
            af0 = lds32h(p);
            af1 = lds32h(p + 8 * MROW1);
            af2 = lds32h(p + 8);
            af3 = lds32h(p + 8 * MROW1 + 8);
        }
        #pragma unroll
        for (int q = 0; q < 2; q++){
            int nt = (ntp << 1) + q;
            const __half* p = sMT + ((nt << 3) + fg) * MROW1 + kb;
            uint32_t b0 = lds32h(p);
            uint32_t b1 = lds32h(p + 8);
            asm volatile(
                "mma.sync.aligned.m16n8k16.row.col.f32.f16.f16.f32 "
                "{%0,%1,%2,%3}, {%4,%5,%6,%7}, {%8,%9}, {%0,%1,%2,%3};"
                : "+f"(acc1[q][0]), "+f"(acc1[q][1]),
                  "+f"(acc1[q][2]), "+f"(acc1[q][3])
                : "r"(af0), "r"(af1), "r"(af2), "r"(af3),
                  "r"(b0), "r"(b1));
        }
    }
    float lsum = 0.f, lss = 0.f;
    #pragma unroll
    for (int q = 0; q < 2; q++)
        #pragma unroll
        for (int c = 0; c < 4; c++){
            float v = acc1[q][c];
            lsum += v; lss += v * v;
        }
    float2 sv = block_reduce_sum2(lsum, lss, red);
    float mu  = sv.x * (1.f / 2048.f);
    float var = sv.y * (1.f / 2048.f) - mu * mu;
    float inv = rsqrtf(var + 1e-5f);
    #pragma unroll
    for (int q = 0; q < 2; q++){
        int nt = (ntp << 1) + q;
        #pragma unroll
        for (int half = 0; half < 2; half++){
            int p = (mt1 << 4) + fg + half * 8;
            int d = (nt << 3) + (tg << 1);
            float v0 = (acc1[q][half * 2 + 0] - mu) * inv; v0 = v0 > 0.f ? v0 : 0.f;
            float v1 = (acc1[q][half * 2 + 1] - mu) * inv; v1 = v1 > 0.f ? v1 : 0.f;
            h1T[(d    ) * MROW + p] = __float2half_rn(v0);
            h1T[(d + 1) * MROW + p] = __float2half_rn(v1);
        }
    }
    __syncthreads();

    // ---- phase 2: h2 = S @ h1 via HMMA ----
    float acc[8][4];
    #pragma unroll
    for (int nt = 0; nt < 8; nt++)
        #pragma unroll
        for (int c = 0; c < 4; c++) acc[nt][c] = 0.f;

    #pragma unroll
    for (int ks = 0; ks < 2; ks++){
        int kb = (ks << 4) + (tg << 1);
        uint32_t af0, af1, af2, af3;
        {
            const __half* p = sS + ((warp << 4) + fg) * MROW + kb;
            af0 = lds32h(p);
            af1 = lds32h(p + 8 * MROW);
            af2 = lds32h(p + 8);
            af3 = lds32h(p + 8 * MROW + 8);
        }
        #pragma unroll
        for (int nt = 0; nt < 8; nt++){
            const __half* p = h1T + ((nt << 3) + fg) * MROW + kb;
            uint32_t b0 = lds32h(p);
            uint32_t b1 = lds32h(p + 8);
            asm volatile(
                "mma.sync.aligned.m16n8k16.row.col.f32.f16.f16.f32 "
                "{%0,%1,%2,%3}, {%4,%5,%6,%7}, {%8,%9}, {%0,%1,%2,%3};"
                : "+f"(acc[nt][0]), "+f"(acc[nt][1]),
                  "+f"(acc[nt][2]), "+f"(acc[nt][3])
                : "r"(af0), "r"(af1), "r"(af2), "r"(af3),
                  "r"(b0), "r"(b1));
        }
    }

    lsum = 0.f; lss = 0.f;
    #pragma unroll
    for (int nt = 0; nt < 8; nt++)
        #pragma unroll
        for (int c = 0; c < 4; c++){
            float v = acc[nt][c];
            lsum += v; lss += v * v;
        }
    sv = block_reduce_sum2(lsum, lss, red);
    mu  = sv.x * (1.f / 8192.f);
    var = sv.y * (1.f / 8192.f) - mu * mu;
    inv = rsqrtf(var + 1e-5f);
    long long base = (long long)bn * GB_GTOT + g * 8192;
    #pragma unroll
    for (int half = 0; half < 2; half++){
        int o = (warp << 4) + fg + half * 8;
        #pragma unroll
        for (int nt = 0; nt < 8; nt++){
            int d = (nt << 3) + (tg << 1);
            float v0 = (acc[nt][half * 2 + 0] - mu) * inv; v0 = v0 > 0.f ? v0 : 0.f;
            float v1 = (acc[nt][half * 2 + 1] - mu) * inv; v1 = v1 > 0.f ? v1 : 0.f;
            *(__half2*)&Hh[base + o * 64 + d] = __floats2half2_rn(v0, v1);
        }
    }
}

// ---------------- split-K reduce + residual + LN1 affine ----------------
__global__ __launch_bounds__(256) void k_final(const float* __restrict__ qf,
                                               const float* __restrict__ op_b,
                                               const float* __restrict__ ln_g,
                                               const float* __restrict__ ln_b,
                                               const float* __restrict__ partial,
                                               float* __restrict__ out)
{
    __shared__ float red[18];
    int bn = blockIdx.x, j = threadIdx.x;
    float x = qf[(long long)bn * 256 + j] + op_b[j];
    #pragma unroll
    for (int sk = 0; sk < 32; sk++)
        x += partial[((long long)sk * GB_BN + bn) * 256 + j];
    float2 sv = block_reduce_sum2(x, x * x, red);
    float mu  = sv.x * (1.f / 256.f);
    float var = sv.y * (1.f / 256.f) - mu * mu;
    float inv = rsqrtf(var + 1e-5f);
    out[(long long)bn * 256 + j] = fmaf((x - mu) * inv, ln_g[j], ln_b[j]);
}

// ---------------- launcher ----------------
extern "C" void kernel_launch(void* const* d_in, const int* in_sizes, int n_in,
                              void* d_out, int out_size)
{
    (void)in_sizes; (void)n_in; (void)out_size;
    const float* feat[4];
    for (int i = 0; i < 4; i++) feat[i] = (const float*)d_in[i];
    const float* qf    = (const float*)d_in[4];
    const float* roi   = (const float*)d_in[5];
    const float* off_w = (const float*)d_in[6];
    const float* off_b = (const float*)d_in[7];
    const float* pg_w  = (const float*)d_in[8];
    const float* pg_b  = (const float*)d_in[9];
    const float* op_w  = (const float*)d_in[10];
    const float* op_b  = (const float*)d_in[11];
    const float* ln_g  = (const float*)d_in[12];
    const float* ln_b  = (const float*)d_in[13];

    float *partial, *offs;
    __half *featTh, *sampledh, *paramsh, *Hh, *qfh, *pgwh, *opwh, *offwh;
    cudaGetSymbolAddress((void**)&featTh,   g_featTh);
    cudaGetSymbolAddress((void**)&sampledh, g_sampledh);
    cudaGetSymbolAddress((void**)&paramsh,  g_paramsh);
    cudaGetSymbolAddress((void**)&partial,  g_partial);
    cudaGetSymbolAddress((void**)&offs,     g_offs);
    cudaGetSymbolAddress((void**)&Hh,       g_Hh);
    cudaGetSymbolAddress((void**)&qfh,      g_qfh);
    cudaGetSymbolAddress((void**)&pgwh,     g_pgwh);
    cudaGetSymbolAddress((void**)&opwh,     g_opwh);
    cudaGetSymbolAddress((void**)&offwh,    g_offwh);

    const int LHW[4] = {16000, 4000, 1000, 260};
    const long long LOFF[4] = {0, 16384000, 20480000, 21504000};
    for (int l = 0; l < 4; l++)
        k_transpose<<<dim3(16, (LHW[l] + 63) / 64), 256>>>(feat[l], featTh + LOFF[l], LHW[l]);

    // conversions
    k_half<<<(307200 + 255) / 256, 256>>>(qf, qfh, 307200);
    k_tconv<<<dim3(1024, 8),  256>>>(pg_w, pgwh, 256, 32768);   // -> [32768][256]
    k_tconv<<<dim3(8, 1024),  256>>>(op_w, opwh, 32768, 256);   // -> [256][32768]
    k_tconv<<<dim3(12, 8),    256>>>(off_w, offwh, 256, 384);   // -> [384][256]

    // GEMM0: offs(1200x384) = qf @ off_w + off_b
    k_mma_gemm<float><<<dim3(3, 10, 1), 256>>>(
        qfh, 256, offwh, 256,
        offs, 384, 0LL, GB_BN, 256, off_b);

    k_sample<<<GB_BN, 256>>>(offs, roi, featTh, sampledh);

    // GEMM1: params(1200x32768, fp16) = qf @ pg_w
    k_mma_gemm<__half><<<dim3(256, 10, 1), 256>>>(
        qfh, 256, pgwh, 256,
        paramsh, 32768, 0LL, GB_BN, 256, pg_b);

    k_mix<<<GB_BN * 4, 256>>>(paramsh, sampledh, Hh);

    // GEMM2: partial[z](1200x256, fp32) = H @ op_w
    k_mma_gemm<float><<<dim3(2, 10, 32), 256>>>(
        Hh, 32768, opwh, 32768,
        partial, 256, 307200LL, GB_BN, 1024, (const float*)nullptr);

    k_final<<<GB_BN, 256>>>(qf, op_b, ln_g, ln_b, partial, (float*)d_out);
}